// round 1
// baseline (speedup 1.0000x reference)
#include <cuda_runtime.h>
#include <math.h>

// Problem constants
#define Bdim 2
#define Nn   2048
#define Ff   64
#define Cc   64
#define Ll   4
#define Kk   (Nn * Ll)      // 8192, flattened (j,l) contraction dim
#define SPLITK 4
#define BM   64
#define BK   32
#define PARTW 68            // 64 term3 cols + 4 deg cols

// Scratch (static device globals: allocation-free per harness rules)
__device__ float g_W3V[(size_t)Bdim * Kk * Cc];            // [b][j*4+l][c]
__device__ float g_W2V[(size_t)Bdim * Nn * Ll * Cc];       // [b][i][l][c]
__device__ float g_T1 [(size_t)Bdim * Nn * Cc];            // [b][i][c]
__device__ float g_part[(size_t)SPLITK * Bdim * Nn * PARTW];

// ---------------- packed f32x2 helpers ----------------
__device__ __forceinline__ unsigned long long pack2(float x, float y) {
    unsigned long long r;
    asm("mov.b64 %0, {%1, %2};" : "=l"(r) : "f"(x), "f"(y));
    return r;
}
__device__ __forceinline__ void unpack2(unsigned long long v, float &x, float &y) {
    asm("mov.b64 {%0, %1}, %2;" : "=f"(x), "=f"(y) : "l"(v));
}
__device__ __forceinline__ void ffma2(unsigned long long &d,
                                      unsigned long long a,
                                      unsigned long long b) {
    // packed fp32 fma: d.lo += a.lo*b.lo ; d.hi += a.hi*b.hi  (exact fp32 semantics)
    asm("fma.rn.f32x2 %0, %1, %2, %0;" : "+l"(d) : "l"(a), "l"(b));
}

// ---------------- precompute: W3V, W2V, T1 ----------------
// grid (Nn, Bdim), 256 threads. Block = one (b, j) row of V.
__global__ void precompute_kernel(const float* __restrict__ V,
                                  const float* __restrict__ w1,
                                  const float* __restrict__ w2,
                                  const float* __restrict__ w3) {
    const int j = blockIdx.x, b = blockIdx.y;
    const int tid = threadIdx.x;
    __shared__ float Vs[Ff];
    if (tid < Ff) Vs[tid] = V[((size_t)b * Nn + j) * Ff + tid];
    __syncthreads();

    const int l = tid >> 6;        // 0..3
    const int c = tid & 63;        // 0..63
    float acc3 = 0.f, acc2 = 0.f;
#pragma unroll 8
    for (int f = 0; f < Ff; f++) {
        const float v = Vs[f];
        acc3 = fmaf(v, w3[(l * Ff + f) * Cc + c], acc3);
        acc2 = fmaf(v, w2[(l * Ff + f) * Cc + c], acc2);
    }
    g_W3V[((size_t)b * Kk + (size_t)j * Ll + l) * Cc + c] = acc3;
    g_W2V[(((size_t)b * Nn + j) * Ll + l) * Cc + c]       = acc2;

    if (tid < Cc) {
        float a = 0.f;
#pragma unroll 8
        for (int f = 0; f < Ff; f++) a = fmaf(Vs[f], w1[f * Cc + tid], a);
        g_T1[((size_t)b * Nn + j) * Cc + tid] = a;
    }
}

// ---------------- main GEMM: term3 partials + deg partials ----------------
// grid (Nn/BM, Bdim, SPLITK), 256 threads.
// C_part[s][b][i][c] = sum over K-slice of A_flat[b,i,k] * W3V[b,k,c]
// cols 64..67 carry deg[b,i,l] partials (fused from A staging).
__global__ __launch_bounds__(256, 2)
void gemm_kernel(const float* __restrict__ A) {
    const int mt = blockIdx.x, b = blockIdx.y, s = blockIdx.z;
    const int tid = threadIdx.x;
    const int i0 = mt * BM;
    const int k0 = s * (Kk / SPLITK);

    __shared__ unsigned long long As2[BK * 65];  // [kk][row], value duplicated (a,a); pad 65 vs banks
    __shared__ float4 Bs4[BK * 16];              // [kk][c/4]
    __shared__ float degS[BM * Ll];

    const float* Ap = A + ((size_t)b * Nn + i0) * (size_t)Kk + k0;
    const float* Bp = g_W3V + ((size_t)b * Kk + k0) * Cc;

    // global-load mapping
    const int arow = tid >> 3;            // 0..31 (also +32)
    const int ac4  = (tid & 7) * 4;       // k offset 0..28
    const int bkk  = tid >> 4;            // 0..15 (also +16)
    const int bc4  = tid & 15;            // float4 col 0..15
    // compute mapping: 16x16 threads, 4x4 outputs each
    const int ty = tid >> 4;
    const int tx = tid & 15;

    degS[tid] = 0.f;
    float degA[8];                        // [rowhalf*4 + l]
#pragma unroll
    for (int i = 0; i < 8; i++) degA[i] = 0.f;

    unsigned long long acc[4][2];
#pragma unroll
    for (int i = 0; i < 4; i++) { acc[i][0] = 0ULL; acc[i][1] = 0ULL; }

    // prefetch tile 0
    float4 ra0 = *(const float4*)(Ap + (size_t)arow * Kk + ac4);
    float4 ra1 = *(const float4*)(Ap + (size_t)(arow + 32) * Kk + ac4);
    float4 rb0 = *(const float4*)(Bp + (size_t)bkk * Cc + bc4 * 4);
    float4 rb1 = *(const float4*)(Bp + (size_t)(bkk + 16) * Cc + bc4 * 4);

    const int NKT = (Kk / SPLITK) / BK;   // 64
    for (int kt = 0; kt < NKT; kt++) {
        __syncthreads();
        // stage A duplicated as f32x2; fuse deg accumulation (l == k & 3 == float4 lane)
        As2[(ac4 + 0) * 65 + arow] = pack2(ra0.x, ra0.x);
        As2[(ac4 + 1) * 65 + arow] = pack2(ra0.y, ra0.y);
        As2[(ac4 + 2) * 65 + arow] = pack2(ra0.z, ra0.z);
        As2[(ac4 + 3) * 65 + arow] = pack2(ra0.w, ra0.w);
        As2[(ac4 + 0) * 65 + arow + 32] = pack2(ra1.x, ra1.x);
        As2[(ac4 + 1) * 65 + arow + 32] = pack2(ra1.y, ra1.y);
        As2[(ac4 + 2) * 65 + arow + 32] = pack2(ra1.z, ra1.z);
        As2[(ac4 + 3) * 65 + arow + 32] = pack2(ra1.w, ra1.w);
        degA[0] += ra0.x; degA[1] += ra0.y; degA[2] += ra0.z; degA[3] += ra0.w;
        degA[4] += ra1.x; degA[5] += ra1.y; degA[6] += ra1.z; degA[7] += ra1.w;
        Bs4[bkk * 16 + bc4]        = rb0;
        Bs4[(bkk + 16) * 16 + bc4] = rb1;
        __syncthreads();

        if (kt + 1 < NKT) {   // prefetch next tile, overlaps with compute below
            const float* Ap2 = Ap + (kt + 1) * BK;
            ra0 = *(const float4*)(Ap2 + (size_t)arow * Kk + ac4);
            ra1 = *(const float4*)(Ap2 + (size_t)(arow + 32) * Kk + ac4);
            const float* Bp2 = Bp + (size_t)(kt + 1) * BK * Cc;
            rb0 = *(const float4*)(Bp2 + (size_t)bkk * Cc + bc4 * 4);
            rb1 = *(const float4*)(Bp2 + (size_t)(bkk + 16) * Cc + bc4 * 4);
        }

#pragma unroll 8
        for (int kk = 0; kk < BK; kk++) {
            const unsigned long long a0 = As2[kk * 65 + ty * 4 + 0];
            const unsigned long long a1 = As2[kk * 65 + ty * 4 + 1];
            const unsigned long long a2 = As2[kk * 65 + ty * 4 + 2];
            const unsigned long long a3 = As2[kk * 65 + ty * 4 + 3];
            const ulonglong2 bv = ((const ulonglong2*)Bs4)[kk * 16 + tx];
            ffma2(acc[0][0], a0, bv.x); ffma2(acc[0][1], a0, bv.y);
            ffma2(acc[1][0], a1, bv.x); ffma2(acc[1][1], a1, bv.y);
            ffma2(acc[2][0], a2, bv.x); ffma2(acc[2][1], a2, bv.y);
            ffma2(acc[3][0], a3, bv.x); ffma2(acc[3][1], a3, bv.y);
        }
    }

    // reduce deg partials across the 8 threads that share each (row, l)
#pragma unroll
    for (int i = 0; i < 4; i++) {
        atomicAdd(&degS[arow * 4 + i],        degA[i]);
        atomicAdd(&degS[(arow + 32) * 4 + i], degA[4 + i]);
    }
    __syncthreads();

    float* outp = g_part + (((size_t)s * Bdim + b) * Nn + i0) * PARTW;
#pragma unroll
    for (int i = 0; i < 4; i++) {
        const int row = ty * 4 + i;
        float4 v;
        unpack2(acc[i][0], v.x, v.y);
        unpack2(acc[i][1], v.z, v.w);
        *(float4*)(outp + (size_t)row * PARTW + tx * 4) = v;
    }
    {   // deg columns
        const int row = tid >> 2, l = tid & 3;
        outp[(size_t)row * PARTW + 64 + l] = degS[tid];
    }
}

// ---------------- epilogue: combine terms + sigmoid ----------------
// grid (Nn, Bdim), 64 threads (one per output channel)
__global__ void epilogue_kernel(float* __restrict__ out) {
    const int i = blockIdx.x, b = blockIdx.y, c = threadIdx.x;
    const size_t row = (size_t)b * Nn + i;

    float t3 = 0.f, d0 = 0.f, d1 = 0.f, d2 = 0.f, d3 = 0.f;
#pragma unroll
    for (int s = 0; s < SPLITK; s++) {
        const float* p = g_part + (((size_t)s * Bdim + b) * Nn + i) * PARTW;
        t3 += p[c];
        d0 += p[64]; d1 += p[65]; d2 += p[66]; d3 += p[67];
    }
    const float* w2v = g_W2V + row * (Ll * Cc);
    float x = g_T1[row * Cc + c]
            + d0 * w2v[0 * Cc + c] + d1 * w2v[1 * Cc + c]
            + d2 * w2v[2 * Cc + c] + d3 * w2v[3 * Cc + c]
            - t3;
    out[row * Cc + c] = 1.f / (1.f + expf(-x));
}

// ---------------- launch ----------------
extern "C" void kernel_launch(void* const* d_in, const int* in_sizes, int n_in,
                              void* d_out, int out_size) {
    const float* V  = (const float*)d_in[0];
    const float* A  = (const float*)d_in[1];
    const float* w1 = (const float*)d_in[2];
    const float* w2 = (const float*)d_in[3];
    const float* w3 = (const float*)d_in[4];
    float* out = (float*)d_out;

    precompute_kernel<<<dim3(Nn, Bdim), 256>>>(V, w1, w2, w3);
    gemm_kernel<<<dim3(Nn / BM, Bdim, SPLITK), 256>>>(A);
    epilogue_kernel<<<dim3(Nn, Bdim), Cc>>>(out);
}

// round 3
// speedup vs baseline: 2.4801x; 2.4801x over previous
#include <cuda_runtime.h>
#include <cstdint>
#include <math.h>

// ---------------- problem constants ----------------
#define Bdim 2
#define Nn   2048
#define Ff   64
#define Cc   64
#define Ll   4
#define Kk   (Nn*Ll)            // 8192
#define SPLITK 16
#define KSLICE (Kk/SPLITK)      // 512
#define BM 128
#define BK 32                   // fp32 elements per K tile (128 bytes)
#define NKT (KSLICE/BK)         // 16
#define PARTW 68                // 64 term3 + 4 deg

// ---------------- scratch (static device globals) ----------------
__device__ __align__(16) float g_W3VT[(size_t)Bdim*Cc*Kk];       // [b][c][k]  (tf32 values)
__device__ __align__(16) float g_W2V [(size_t)Bdim*Nn*Ll*Cc];
__device__ __align__(16) float g_T1  [(size_t)Bdim*Nn*Cc];
__device__ __align__(16) float g_part[(size_t)SPLITK*Bdim*Nn*PARTW];

// ---------------- helpers ----------------
__device__ __forceinline__ uint32_t smem_u32(const void* p) {
    uint32_t a;
    asm("{ .reg .u64 t; cvta.to.shared.u64 t, %1; cvt.u32.u64 %0, t; }" : "=r"(a) : "l"(p));
    return a;
}
__device__ __forceinline__ float to_tf32(float x) {
    uint32_t u;
    asm("cvt.rna.tf32.f32 %0, %1;" : "=r"(u) : "f"(x));
    return __uint_as_float(u);
}
__device__ __forceinline__ unsigned long long pack2(float x, float y) {
    unsigned long long r; asm("mov.b64 %0, {%1, %2};" : "=l"(r) : "f"(x), "f"(y)); return r;
}
__device__ __forceinline__ void unpack2(unsigned long long v, float &x, float &y) {
    asm("mov.b64 {%0, %1}, %2;" : "=f"(x), "=f"(y) : "l"(v));
}
__device__ __forceinline__ void ffma2(unsigned long long &d, unsigned long long a, unsigned long long b) {
    asm("fma.rn.f32x2 %0, %1, %2, %0;" : "+l"(d) : "l"(a), "l"(b));
}
__device__ __forceinline__ uint32_t sw128(uint32_t off) { return off ^ ((off >> 3) & 0x70); }

#define LDSM_X4(r, addr)                                                         \
    asm volatile("ldmatrix.sync.aligned.m8n8.x4.shared.b16 {%0,%1,%2,%3}, [%4];" \
        : "=r"((r)[0]), "=r"((r)[1]), "=r"((r)[2]), "=r"((r)[3]) : "r"(addr))

#define MMA_TF32(c, a, b0v, b1v)                                                 \
    asm volatile("mma.sync.aligned.m16n8k8.row.col.f32.tf32.tf32.f32 "           \
        "{%0,%1,%2,%3}, {%4,%5,%6,%7}, {%8,%9}, {%0,%1,%2,%3};"                  \
        : "+f"((c)[0]), "+f"((c)[1]), "+f"((c)[2]), "+f"((c)[3])                  \
        : "r"((a)[0]), "r"((a)[1]), "r"((a)[2]), "r"((a)[3]), "r"(b0v), "r"(b1v))

// ---------------- precompute: W3V^T (tf32), W2V, T1 ----------------
// grid (Nn/8, Bdim), 256 threads. 8 j-rows per block amortize weight loads.
__global__ void precompute_kernel(const float* __restrict__ V,
                                  const float* __restrict__ w1,
                                  const float* __restrict__ w2,
                                  const float* __restrict__ w3) {
    const int jt = blockIdx.x, b = blockIdx.y;
    const int j0 = jt * 8;
    const int tid = threadIdx.x;

    __shared__ __align__(16) float Vst[Ff][8];   // [f][jj]
#pragma unroll
    for (int it = 0; it < 2; it++) {
        int id2 = tid + it * 256;                // 0..511
        int jj = id2 >> 6, f = id2 & 63;
        Vst[f][jj] = V[((size_t)b * Nn + j0 + jj) * Ff + f];
    }
    __syncthreads();

    const int l = tid >> 6, c = tid & 63;
    unsigned long long a3[4] = {0,0,0,0}, a2[4] = {0,0,0,0};
#pragma unroll 8
    for (int f = 0; f < Ff; f++) {
        const float w3v = w3[(l * Ff + f) * Cc + c];
        const float w2v = w2[(l * Ff + f) * Cc + c];
        const unsigned long long w3p = pack2(w3v, w3v), w2p = pack2(w2v, w2v);
        const unsigned long long* vp = (const unsigned long long*)Vst[f];
#pragma unroll
        for (int p = 0; p < 4; p++) { ffma2(a3[p], vp[p], w3p); ffma2(a2[p], vp[p], w2p); }
    }
#pragma unroll
    for (int p = 0; p < 4; p++) {
        float x, y;
        unpack2(a3[p], x, y);
        const int j = j0 + 2 * p;
        g_W3VT[((size_t)b * Cc + c) * Kk + (size_t)j * Ll + l]       = to_tf32(x);
        g_W3VT[((size_t)b * Cc + c) * Kk + (size_t)(j + 1) * Ll + l] = to_tf32(y);
        unpack2(a2[p], x, y);
        g_W2V[(((size_t)b * Nn + j)     * Ll + l) * Cc + c] = x;
        g_W2V[(((size_t)b * Nn + j + 1) * Ll + l) * Cc + c] = y;
    }
    // T1 = V @ w1
    if (tid < Cc) {
        float acc[8] = {0,0,0,0,0,0,0,0};
#pragma unroll 8
        for (int f = 0; f < Ff; f++) {
            const float w = w1[f * Cc + tid];
#pragma unroll
            for (int jj = 0; jj < 8; jj++) acc[jj] = fmaf(Vst[f][jj], w, acc[jj]);
        }
#pragma unroll
        for (int jj = 0; jj < 8; jj++)
            g_T1[((size_t)b * Nn + j0 + jj) * Cc + tid] = acc[jj];
    }
}

// ---------------- main GEMM: mma.sync tf32, term3 + fused deg ----------------
// grid (Nn/BM, Bdim, SPLITK) = (16,2,16), 256 threads (8 warps).
// Warp tile 32x32: wm = wid&3 (rows), wn = wid>>2 (cols).
__global__ __launch_bounds__(256)
void gemm_kernel(const float* __restrict__ A) {
    __shared__ __align__(128) float sA[BM * BK];   // 16 KB, 128B rows, SW128 swizzled
    __shared__ __align__(128) float sB[Cc * BK];   //  8 KB, n-major (row=c, col=k)
    __shared__ float degS[BM * Ll];                //  2 KB

    const int mtb = blockIdx.x, b = blockIdx.y, s = blockIdx.z;
    const int i0 = mtb * BM, k0 = s * KSLICE;
    const int tid = threadIdx.x, wid = tid >> 5, lid = tid & 31;
    const int wm = wid & 3, wn = wid >> 2;

    degS[tid] = 0.f; degS[tid + 256] = 0.f;

    const float* Ab = A      + ((size_t)b * Nn + i0) * Kk + k0;
    const float* Bb = g_W3VT + ((size_t)b * Cc) * Kk + k0;

    const uint32_t sAu = smem_u32(sA), sBu = smem_u32(sB);

    // per-lane ldmatrix quad addressing (byte offsets, before swizzle/ks)
    const int q = lid >> 3, rr = lid & 7;
    uint32_t aOff[2], bOff[2];
#pragma unroll
    for (int mt = 0; mt < 2; mt++)
        aOff[mt] = (uint32_t)((wm * 32 + mt * 16 + rr + (q & 1) * 8) * 128 + (q >> 1) * 16);
#pragma unroll
    for (int h = 0; h < 2; h++)
        bOff[h]  = (uint32_t)((wn * 32 + h * 16 + rr + (q >> 1) * 8) * 128 + (q & 1) * 16);

    float4 ra[4], rb[2];
    float degA[4][4];
#pragma unroll
    for (int i = 0; i < 4; i++)
#pragma unroll
        for (int e = 0; e < 4; e++) degA[i][e] = 0.f;

    float acc[2][4][4];
#pragma unroll
    for (int mt = 0; mt < 2; mt++)
#pragma unroll
        for (int nt = 0; nt < 4; nt++)
#pragma unroll
            for (int e = 0; e < 4; e++) acc[mt][nt][e] = 0.f;

    auto loadT = [&](int kt) {
#pragma unroll
        for (int it = 0; it < 4; it++) {
            const int idx = it * 256 + tid, row = idx >> 3, f4 = idx & 7;
            ra[it] = *(const float4*)(Ab + (size_t)row * Kk + kt * BK + f4 * 4);
        }
#pragma unroll
        for (int it = 0; it < 2; it++) {
            const int idx = it * 256 + tid, row = idx >> 3, f4 = idx & 7;
            rb[it] = *(const float4*)(Bb + (size_t)row * Kk + kt * BK + f4 * 4);
        }
    };

    loadT(0);

    for (int kt = 0; kt < NKT; kt++) {
        // ---- stage regs -> SMEM (A converted to tf32; deg fused) ----
#pragma unroll
        for (int it = 0; it < 4; it++) {
            const int idx = it * 256 + tid, row = idx >> 3, f4 = idx & 7;
            const uint32_t off = sw128((uint32_t)(row * 128 + f4 * 16));
            float4 t;
            t.x = to_tf32(ra[it].x); t.y = to_tf32(ra[it].y);
            t.z = to_tf32(ra[it].z); t.w = to_tf32(ra[it].w);
            *(float4*)((char*)sA + off) = t;
            degA[it][0] += ra[it].x; degA[it][1] += ra[it].y;
            degA[it][2] += ra[it].z; degA[it][3] += ra[it].w;
        }
#pragma unroll
        for (int it = 0; it < 2; it++) {
            const int idx = it * 256 + tid, row = idx >> 3, f4 = idx & 7;
            const uint32_t off = sw128((uint32_t)(row * 128 + f4 * 16));
            *(float4*)((char*)sB + off) = rb[it];
        }
        __syncthreads();

        if (kt + 1 < NKT) loadT(kt + 1);   // overlap next-tile LDGs with MMA

        // ---- compute BK from SMEM ----
#pragma unroll
        for (int ks = 0; ks < 4; ks++) {
            uint32_t af[2][4], bf[2][4];
#pragma unroll
            for (int mt = 0; mt < 2; mt++) {
                uint32_t o = aOff[mt] + ks * 32;
                LDSM_X4(af[mt], sAu + (o ^ ((o >> 3) & 0x70)));
            }
#pragma unroll
            for (int h = 0; h < 2; h++) {
                uint32_t o = bOff[h] + ks * 32;
                LDSM_X4(bf[h], sBu + (o ^ ((o >> 3) & 0x70)));
            }
#pragma unroll
            for (int mt = 0; mt < 2; mt++)
#pragma unroll
                for (int nt = 0; nt < 4; nt++)
                    MMA_TF32(acc[mt][nt], af[mt], bf[nt >> 1][(nt & 1) * 2], bf[nt >> 1][(nt & 1) * 2 + 1]);
        }
        __syncthreads();
    }

    // ---- deg reduction into SMEM ----
#pragma unroll
    for (int it = 0; it < 4; it++) {
        const int row = it * 32 + (tid >> 3);
#pragma unroll
        for (int e = 0; e < 4; e++) atomicAdd(&degS[row * 4 + e], degA[it][e]);
    }
    __syncthreads();

    // ---- write partials ----
    float* outp = g_part + (((size_t)s * Bdim + b) * Nn + i0) * PARTW;
    const int gid = lid >> 2, tig = lid & 3;
#pragma unroll
    for (int mt = 0; mt < 2; mt++)
#pragma unroll
        for (int nt = 0; nt < 4; nt++) {
            const int r0 = wm * 32 + mt * 16 + gid;
            const int cc = wn * 32 + nt * 8 + 2 * tig;
            float2 v0; v0.x = acc[mt][nt][0]; v0.y = acc[mt][nt][1];
            float2 v1; v1.x = acc[mt][nt][2]; v1.y = acc[mt][nt][3];
            *(float2*)(outp + (size_t)r0 * PARTW + cc)       = v0;
            *(float2*)(outp + (size_t)(r0 + 8) * PARTW + cc) = v1;
        }
#pragma unroll
    for (int it = 0; it < 2; it++) {
        const int idx = it * 256 + tid;            // 0..511 = row*4 + l
        outp[(size_t)(idx >> 2) * PARTW + 64 + (idx & 3)] = degS[idx];
    }
}

// ---------------- epilogue: combine terms + sigmoid ----------------
__global__ void epilogue_kernel(float* __restrict__ out) {
    const int i = blockIdx.x, b = blockIdx.y, c = threadIdx.x;
    const size_t row = (size_t)b * Nn + i;

    float t3 = 0.f, d0 = 0.f, d1 = 0.f, d2 = 0.f, d3 = 0.f;
#pragma unroll
    for (int s = 0; s < SPLITK; s++) {
        const float* p = g_part + (((size_t)s * Bdim + b) * Nn + i) * PARTW;
        t3 += p[c];
        d0 += p[64]; d1 += p[65]; d2 += p[66]; d3 += p[67];
    }
    const float* w2v = g_W2V + row * (Ll * Cc);
    const float x = g_T1[row * Cc + c]
                  + d0 * w2v[0 * Cc + c] + d1 * w2v[1 * Cc + c]
                  + d2 * w2v[2 * Cc + c] + d3 * w2v[3 * Cc + c]
                  - t3;
    out[row * Cc + c] = 1.f / (1.f + expf(-x));
}

// ---------------- launch ----------------
extern "C" void kernel_launch(void* const* d_in, const int* in_sizes, int n_in,
                              void* d_out, int out_size) {
    const float* V  = (const float*)d_in[0];
    const float* A  = (const float*)d_in[1];
    const float* w1 = (const float*)d_in[2];
    const float* w2 = (const float*)d_in[3];
    const float* w3 = (const float*)d_in[4];
    float* out = (float*)d_out;

    precompute_kernel<<<dim3(Nn / 8, Bdim), 256>>>(V, w1, w2, w3);
    gemm_kernel<<<dim3(Nn / BM, Bdim, SPLITK), 256>>>(A);
    epilogue_kernel<<<dim3(Nn, Bdim), Cc>>>(out);
}

// round 5
// speedup vs baseline: 3.7647x; 1.5180x over previous
#include <cuda_runtime.h>
#include <cstdint>
#include <math.h>

// ---------------- problem constants ----------------
#define Bdim 2
#define Nn   2048
#define Ff   64
#define Cc   64
#define Ll   4
#define Kk   (Nn*Ll)            // 8192
#define BM 128
#define BK 32                   // fp32 elements per K tile (128 bytes)
#define NTILES (Kk/BK)          // 256
#define SPLITK 13               // 32 M-tiles * 13 = 416 blocks = 1 wave @ 3/SM
#define PARTW 68                // 64 term3 + 4 deg

// ---------------- scratch (static device globals) ----------------
__device__ __align__(16) float g_W3VT[(size_t)Bdim*Cc*Kk];       // [b][c][k] (tf32 values)
__device__ __align__(16) float g_W2V [(size_t)Bdim*Nn*Ll*Cc];    // [m][l*64+c]
__device__ __align__(16) float g_T1  [(size_t)Bdim*Nn*Cc];
__device__ __align__(16) float g_WTh [576*Ff];                   // [t][f], tf32 hi
__device__ __align__(16) float g_WTl [576*Ff];                   // [t][f], tf32 lo
__device__ __align__(16) float g_part[(size_t)SPLITK*Bdim*Nn*PARTW];

// ---------------- helpers ----------------
__device__ __forceinline__ uint32_t smem_u32(const void* p) {
    uint32_t a;
    asm("{ .reg .u64 t; cvta.to.shared.u64 t, %1; cvt.u32.u64 %0, t; }" : "=r"(a) : "l"(p));
    return a;
}
__device__ __forceinline__ float to_tf32(float x) {
    uint32_t u;
    asm("cvt.rna.tf32.f32 %0, %1;" : "=r"(u) : "f"(x));
    return __uint_as_float(u);
}
__device__ __forceinline__ uint32_t sw128(uint32_t off) { return off ^ ((off >> 3) & 0x70); }

#define CP16(dst, src) \
    asm volatile("cp.async.cg.shared.global [%0], [%1], 16;" \
        :: "r"(dst), "l"(__cvta_generic_to_global(src)) : "memory")
#define CPCOMMIT() asm volatile("cp.async.commit_group;" ::: "memory")
#define CPWAIT(n)  asm volatile("cp.async.wait_group %0;" :: "n"(n) : "memory")

#define LDSM_X4(r, addr)                                                         \
    asm volatile("ldmatrix.sync.aligned.m8n8.x4.shared.b16 {%0,%1,%2,%3}, [%4];" \
        : "=r"((r)[0]), "=r"((r)[1]), "=r"((r)[2]), "=r"((r)[3]) : "r"(addr))

#define MMA_TF32(c, a, b0v, b1v)                                                 \
    asm volatile("mma.sync.aligned.m16n8k8.row.col.f32.tf32.tf32.f32 "           \
        "{%0,%1,%2,%3}, {%4,%5,%6,%7}, {%8,%9}, {%0,%1,%2,%3};"                  \
        : "+f"((c)[0]), "+f"((c)[1]), "+f"((c)[2]), "+f"((c)[3])                  \
        : "r"((a)[0]), "r"((a)[1]), "r"((a)[2]), "r"((a)[3]), "r"(b0v), "r"(b1v))

// ---------------- weight transpose/concat + tf32 split: g_WTh/g_WTl ----------------
// t<256: w3 (l=t>>6, c=t&63); 256<=t<512: w2; t>=512: w1 col (t-512)
__global__ void wtrans_kernel(const float* __restrict__ w1,
                              const float* __restrict__ w2,
                              const float* __restrict__ w3) {
    const int t = blockIdx.x, f = threadIdx.x;
    float v;
    if (t < 256)      v = w3[((t >> 6) * Ff + f) * Cc + (t & 63)];
    else if (t < 512) v = w2[(((t - 256) >> 6) * Ff + f) * Cc + ((t - 256) & 63)];
    else              v = w1[f * Cc + (t - 512)];
    const float hi = to_tf32(v);
    g_WTh[t * Ff + f] = hi;
    g_WTl[t * Ff + f] = to_tf32(v - hi);
}

// ---------------- precompute GEMM (tf32x3): [W3V | W2V | T1] = V @ Wcat ----------------
// grid (32 M-tiles, 9 N-chunks), 256 threads, warp tile 32x32.
__global__ __launch_bounds__(256)
void pregemm_kernel(const float* __restrict__ V) {
    __shared__ __align__(128) float sAhi[BM * BK];   // 16 KB
    __shared__ __align__(128) float sAlo[BM * BK];   // 16 KB
    __shared__ __align__(128) float sBhi[64 * BK];   //  8 KB
    __shared__ __align__(128) float sBlo[64 * BK];   //  8 KB  (total 48 KB)
    const uint32_t aH = smem_u32(sAhi), aL = smem_u32(sAlo);
    const uint32_t bH = smem_u32(sBhi), bL = smem_u32(sBlo);

    const int mtile = blockIdx.x, nc = blockIdx.y;
    const int m0 = mtile * BM;
    const int tid = threadIdx.x, wid = tid >> 5, lid = tid & 31;
    const int wm = wid & 3, wn = wid >> 2;

    const float* Ab  = V + (size_t)m0 * Ff;
    const float* Bh  = g_WTh + (size_t)nc * 64 * Ff;
    const float* Bl  = g_WTl + (size_t)nc * 64 * Ff;

    // ldmatrix quad addressing
    const int q = lid >> 3, rr = lid & 7;
    uint32_t aOff[2], bOff[2];
#pragma unroll
    for (int mt = 0; mt < 2; mt++)
        aOff[mt] = (uint32_t)((wm * 32 + mt * 16 + rr + (q & 1) * 8) * 128 + (q >> 1) * 16);
#pragma unroll
    for (int h = 0; h < 2; h++)
        bOff[h]  = (uint32_t)((wn * 32 + h * 16 + rr + (q >> 1) * 8) * 128 + (q & 1) * 16);

    float acc[2][4][4];
#pragma unroll
    for (int mt = 0; mt < 2; mt++)
#pragma unroll
        for (int nt = 0; nt < 4; nt++)
#pragma unroll
            for (int e = 0; e < 4; e++) acc[mt][nt][e] = 0.f;

    for (int kt = 0; kt < 2; kt++) {
        // stage A (hi/lo split)
#pragma unroll
        for (int it = 0; it < 4; it++) {
            const int idx = it * 256 + tid, row = idx >> 3, f4 = idx & 7;
            const float4 v = *(const float4*)(Ab + (size_t)row * Ff + kt * BK + f4 * 4);
            float4 h, l;
            h.x = to_tf32(v.x); l.x = to_tf32(v.x - h.x);
            h.y = to_tf32(v.y); l.y = to_tf32(v.y - h.y);
            h.z = to_tf32(v.z); l.z = to_tf32(v.z - h.z);
            h.w = to_tf32(v.w); l.w = to_tf32(v.w - h.w);
            const uint32_t off = sw128((uint32_t)(row * 128 + f4 * 16));
            *(float4*)((char*)sAhi + off) = h;
            *(float4*)((char*)sAlo + off) = l;
        }
        // stage B (already split in global)
#pragma unroll
        for (int it = 0; it < 2; it++) {
            const int idx = it * 256 + tid, row = idx >> 3, f4 = idx & 7;
            const uint32_t off = sw128((uint32_t)(row * 128 + f4 * 16));
            *(float4*)((char*)sBhi + off) = *(const float4*)(Bh + (size_t)row * Ff + kt * BK + f4 * 4);
            *(float4*)((char*)sBlo + off) = *(const float4*)(Bl + (size_t)row * Ff + kt * BK + f4 * 4);
        }
        __syncthreads();

#pragma unroll
        for (int ks = 0; ks < 4; ks++) {
            uint32_t afh[2][4], afl[2][4], bfh[2][4], bfl[2][4];
#pragma unroll
            for (int mt = 0; mt < 2; mt++) {
                uint32_t o = aOff[mt] + ks * 32, so = (o ^ ((o >> 3) & 0x70));
                LDSM_X4(afh[mt], aH + so);
                LDSM_X4(afl[mt], aL + so);
            }
#pragma unroll
            for (int h = 0; h < 2; h++) {
                uint32_t o = bOff[h] + ks * 32, so = (o ^ ((o >> 3) & 0x70));
                LDSM_X4(bfh[h], bH + so);
                LDSM_X4(bfl[h], bL + so);
            }
#pragma unroll
            for (int mt = 0; mt < 2; mt++)
#pragma unroll
                for (int nt = 0; nt < 4; nt++) {
                    const int hb = nt >> 1, eb = (nt & 1) * 2;
                    MMA_TF32(acc[mt][nt], afl[mt], bfh[hb][eb], bfh[hb][eb + 1]);
                    MMA_TF32(acc[mt][nt], afh[mt], bfl[hb][eb], bfl[hb][eb + 1]);
                    MMA_TF32(acc[mt][nt], afh[mt], bfh[hb][eb], bfh[hb][eb + 1]);
                }
        }
        __syncthreads();
    }

    // epilogue: route by N-chunk
    const int gid = lid >> 2, tig = lid & 3;
#pragma unroll
    for (int mt = 0; mt < 2; mt++)
#pragma unroll
        for (int nt = 0; nt < 4; nt++)
#pragma unroll
            for (int e = 0; e < 4; e++) {
                const int row = wm * 32 + mt * 16 + gid + (e >> 1) * 8;
                const int col = wn * 32 + nt * 8 + 2 * tig + (e & 1);
                const int m = m0 + row;
                const float v = acc[mt][nt][e];
                if (nc < 4) {
                    const int bb = m >> 11, j = m & 2047;
                    g_W3VT[((size_t)(bb * 64 + col)) * Kk + j * 4 + nc] = to_tf32(v);
                } else if (nc < 8) {
                    g_W2V[(size_t)m * 256 + (nc - 4) * 64 + col] = v;
                } else {
                    g_T1[(size_t)m * 64 + col] = v;
                }
            }
}

// ---------------- main GEMM: term3 + deg-from-fragments ----------------
// grid (16, Bdim, SPLITK), 256 threads (8 warps), warp tile 32x32.
__global__ __launch_bounds__(256, 3)
void gemm_kernel(const float* __restrict__ A) {
    __shared__ __align__(128) uint8_t smemRaw[49152];
    const uint32_t sm = smem_u32(smemRaw);
    const uint32_t sAu[2] = { sm, sm + 16384 };
    const uint32_t sBu[2] = { sm + 32768, sm + 40960 };
    float* degS = (float*)smemRaw;   // aliases sA0 after the main loop

    const int mtb = blockIdx.x, b = blockIdx.y, s = blockIdx.z;
    const int i0 = mtb * BM;
    const int t0 = (s * NTILES) / SPLITK, t1 = ((s + 1) * NTILES) / SPLITK;
    const int nkt = t1 - t0;
    const int tid = threadIdx.x, wid = tid >> 5, lid = tid & 31;
    const int wm = wid & 3, wn = wid >> 2;

    const float* Ab = A      + ((size_t)b * Nn + i0) * Kk;
    const float* Bb = g_W3VT + ((size_t)b * Cc) * Kk;

    auto issue = [&](int kt, int st) {
#pragma unroll
        for (int it = 0; it < 4; it++) {
            const int idx = it * 256 + tid, row = idx >> 3, f4 = idx & 7;
            CP16(sAu[st] + sw128((uint32_t)(row * 128 + f4 * 16)),
                 Ab + (size_t)row * Kk + kt * BK + f4 * 4);
        }
#pragma unroll
        for (int it = 0; it < 2; it++) {
            const int idx = it * 256 + tid, row = idx >> 3, f4 = idx & 7;
            CP16(sBu[st] + sw128((uint32_t)(row * 128 + f4 * 16)),
                 Bb + (size_t)row * Kk + kt * BK + f4 * 4);
        }
    };

    const int q = lid >> 3, rr = lid & 7;
    uint32_t aOff[2], bOff[2];
#pragma unroll
    for (int mt = 0; mt < 2; mt++)
        aOff[mt] = (uint32_t)((wm * 32 + mt * 16 + rr + (q & 1) * 8) * 128 + (q >> 1) * 16);
#pragma unroll
    for (int h = 0; h < 2; h++)
        bOff[h]  = (uint32_t)((wn * 32 + h * 16 + rr + (q >> 1) * 8) * 128 + (q & 1) * 16);

    float acc[2][4][4];
#pragma unroll
    for (int mt = 0; mt < 2; mt++)
#pragma unroll
        for (int nt = 0; nt < 4; nt++)
#pragma unroll
            for (int e = 0; e < 4; e++) acc[mt][nt][e] = 0.f;
    float dacc[4] = {0.f, 0.f, 0.f, 0.f};   // deg accum (wn==0 warps)

    issue(t0, 0); CPCOMMIT();
    if (nkt > 1) issue(t0 + 1, 1);
    CPCOMMIT();

    for (int qq = 0; qq < nkt; qq++) {
        const int st = qq & 1;
        CPWAIT(1);
        __syncthreads();
#pragma unroll
        for (int ks = 0; ks < 4; ks++) {
            uint32_t af[2][4], bf[2][4];
#pragma unroll
            for (int mt = 0; mt < 2; mt++) {
                uint32_t o = aOff[mt] + ks * 32;
                LDSM_X4(af[mt], sAu[st] + (o ^ ((o >> 3) & 0x70)));
            }
#pragma unroll
            for (int h = 0; h < 2; h++) {
                uint32_t o = bOff[h] + ks * 32;
                LDSM_X4(bf[h], sBu[st] + (o ^ ((o >> 3) & 0x70)));
            }
            if (wn == 0) {   // deg from A fragments: l = lane&3 exactly
#pragma unroll
                for (int mt = 0; mt < 2; mt++) {
                    dacc[mt * 2]     += __uint_as_float(af[mt][0]) + __uint_as_float(af[mt][2]);
                    dacc[mt * 2 + 1] += __uint_as_float(af[mt][1]) + __uint_as_float(af[mt][3]);
                }
            }
#pragma unroll
            for (int mt = 0; mt < 2; mt++)
#pragma unroll
                for (int nt = 0; nt < 4; nt++)
                    MMA_TF32(acc[mt][nt], af[mt], bf[nt >> 1][(nt & 1) * 2], bf[nt >> 1][(nt & 1) * 2 + 1]);
        }
        __syncthreads();
        if (qq + 2 < nkt) issue(t0 + qq + 2, st);
        CPCOMMIT();
    }

    // deg: unique (row, l) per thread among wn==0 warps -> plain stores
    const int gid = lid >> 2, tig = lid & 3;
    __syncthreads();
    if (wn == 0) {
#pragma unroll
        for (int i = 0; i < 4; i++) {
            const int row = wm * 32 + (i >> 1) * 16 + (i & 1) * 8 + gid;
            degS[row * 4 + tig] = dacc[i];
        }
    }
    __syncthreads();

    // write partials
    float* outp = g_part + (((size_t)s * Bdim + b) * Nn + i0) * PARTW;
#pragma unroll
    for (int mt = 0; mt < 2; mt++)
#pragma unroll
        for (int nt = 0; nt < 4; nt++) {
            const int r0 = wm * 32 + mt * 16 + gid;
            const int cc = wn * 32 + nt * 8 + 2 * tig;
            float2 v0; v0.x = acc[mt][nt][0]; v0.y = acc[mt][nt][1];
            float2 v1; v1.x = acc[mt][nt][2]; v1.y = acc[mt][nt][3];
            *(float2*)(outp + (size_t)r0 * PARTW + cc)       = v0;
            *(float2*)(outp + (size_t)(r0 + 8) * PARTW + cc) = v1;
        }
#pragma unroll
    for (int it = 0; it < 2; it++) {
        const int idx = it * 256 + tid;    // row*4 + l
        outp[(size_t)(idx >> 2) * PARTW + 64 + (idx & 3)] = degS[idx];
    }
}

// ---------------- epilogue: combine terms + sigmoid ----------------
__global__ void epilogue_kernel(float* __restrict__ out) {
    const int i = blockIdx.x, b = blockIdx.y, c = threadIdx.x;
    const size_t row = (size_t)b * Nn + i;

    float t3 = 0.f, d0 = 0.f, d1 = 0.f, d2 = 0.f, d3 = 0.f;
#pragma unroll
    for (int s = 0; s < SPLITK; s++) {
        const float* p = g_part + (((size_t)s * Bdim + b) * Nn + i) * PARTW;
        t3 += p[c];
        d0 += p[64]; d1 += p[65]; d2 += p[66]; d3 += p[67];
    }
    const float* w2v = g_W2V + row * (Ll * Cc);
    const float x = g_T1[row * Cc + c]
                  + d0 * w2v[0 * Cc + c] + d1 * w2v[1 * Cc + c]
                  + d2 * w2v[2 * Cc + c] + d3 * w2v[3 * Cc + c]
                  - t3;
    out[row * Cc + c] = 1.f / (1.f + expf(-x));
}

// ---------------- launch ----------------
extern "C" void kernel_launch(void* const* d_in, const int* in_sizes, int n_in,
                              void* d_out, int out_size) {
    const float* V  = (const float*)d_in[0];
    const float* A  = (const float*)d_in[1];
    const float* w1 = (const float*)d_in[2];
    const float* w2 = (const float*)d_in[3];
    const float* w3 = (const float*)d_in[4];
    float* out = (float*)d_out;

    wtrans_kernel<<<576, 64>>>(w1, w2, w3);
    pregemm_kernel<<<dim3(32, 9), 256>>>(V);
    gemm_kernel<<<dim3(Nn / BM, Bdim, SPLITK), 256>>>(A);
    epilogue_kernel<<<dim3(Nn, Bdim), Cc>>>(out);
}

// round 6
// speedup vs baseline: 3.9215x; 1.0416x over previous
#include <cuda_runtime.h>
#include <cstdint>
#include <math.h>

// ---------------- problem constants ----------------
#define Bdim 2
#define Nn   2048
#define Ff   64
#define Cc   64
#define Ll   4
#define Kk   (Nn*Ll)            // 8192
#define BM 128
#define BK 32                   // fp32 elements per K tile (128 bytes)
#define NTILES (Kk/BK)          // 256
#define SPLITK 13               // 32 M-tiles * 13 = 416 blocks = 1 wave @ 3/SM
#define PARTW 68                // 64 term3 + 4 deg

// ---------------- scratch (static device globals) ----------------
__device__ __align__(16) float g_W3VT[(size_t)Bdim*Cc*Kk];       // [b][c][k] (tf32 values)
__device__ __align__(16) float g_W2V [(size_t)Bdim*Nn*Ll*Cc];    // [m][l*64+c]
__device__ __align__(16) float g_T1  [(size_t)Bdim*Nn*Cc];
__device__ __align__(16) float g_WTh [576*Ff];                   // [t][f], tf32 hi
__device__ __align__(16) float g_WTl [576*Ff];                   // [t][f], tf32 lo
__device__ __align__(16) float g_part[(size_t)SPLITK*Bdim*Nn*PARTW];

// ---------------- helpers ----------------
__device__ __forceinline__ uint32_t smem_u32(const void* p) {
    uint32_t a;
    asm("{ .reg .u64 t; cvta.to.shared.u64 t, %1; cvt.u32.u64 %0, t; }" : "=r"(a) : "l"(p));
    return a;
}
__device__ __forceinline__ float to_tf32(float x) {
    uint32_t u;
    asm("cvt.rna.tf32.f32 %0, %1;" : "=r"(u) : "f"(x));
    return __uint_as_float(u);
}
__device__ __forceinline__ uint32_t sw128(uint32_t off) { return off ^ ((off >> 3) & 0x70); }

#define CP16(dst, src) \
    asm volatile("cp.async.cg.shared.global [%0], [%1], 16;" \
        :: "r"(dst), "l"(__cvta_generic_to_global(src)) : "memory")
#define CPCOMMIT() asm volatile("cp.async.commit_group;" ::: "memory")
#define CPWAIT(n)  asm volatile("cp.async.wait_group %0;" :: "n"(n) : "memory")

#define LDSM_X4(r, addr)                                                         \
    asm volatile("ldmatrix.sync.aligned.m8n8.x4.shared.b16 {%0,%1,%2,%3}, [%4];" \
        : "=r"((r)[0]), "=r"((r)[1]), "=r"((r)[2]), "=r"((r)[3]) : "r"(addr))

#define MMA_TF32(c, a, b0v, b1v)                                                 \
    asm volatile("mma.sync.aligned.m16n8k8.row.col.f32.tf32.tf32.f32 "           \
        "{%0,%1,%2,%3}, {%4,%5,%6,%7}, {%8,%9}, {%0,%1,%2,%3};"                  \
        : "+f"((c)[0]), "+f"((c)[1]), "+f"((c)[2]), "+f"((c)[3])                  \
        : "r"((a)[0]), "r"((a)[1]), "r"((a)[2]), "r"((a)[3]), "r"(b0v), "r"(b1v))

// ---------------- weight transpose/concat + tf32 split: g_WTh/g_WTl ----------------
// t<256: w3 (l=t>>6, c=t&63); 256<=t<512: w2; t>=512: w1 col (t-512)
__global__ void wtrans_kernel(const float* __restrict__ w1,
                              const float* __restrict__ w2,
                              const float* __restrict__ w3) {
    const int t = blockIdx.x, f = threadIdx.x;
    float v;
    if (t < 256)      v = w3[((t >> 6) * Ff + f) * Cc + (t & 63)];
    else if (t < 512) v = w2[(((t - 256) >> 6) * Ff + f) * Cc + ((t - 256) & 63)];
    else              v = w1[f * Cc + (t - 512)];
    const float hi = to_tf32(v);
    g_WTh[t * Ff + f] = hi;
    g_WTl[t * Ff + f] = to_tf32(v - hi);
}

// ---------------- precompute GEMM (tf32x3): [W3V | W2V | T1] = V @ Wcat ----------------
// grid (32 M-tiles, 9 N-chunks), 256 threads, warp tile 32x32.
__global__ __launch_bounds__(256)
void pregemm_kernel(const float* __restrict__ V) {
    __shared__ __align__(128) float sAhi[BM * BK];   // 16 KB
    __shared__ __align__(128) float sAlo[BM * BK];   // 16 KB
    __shared__ __align__(128) float sBhi[64 * BK];   //  8 KB
    __shared__ __align__(128) float sBlo[64 * BK];   //  8 KB  (total 48 KB)
    const uint32_t aH = smem_u32(sAhi), aL = smem_u32(sAlo);
    const uint32_t bH = smem_u32(sBhi), bL = smem_u32(sBlo);

    const int mtile = blockIdx.x, nc = blockIdx.y;
    const int m0 = mtile * BM;
    const int tid = threadIdx.x, wid = tid >> 5, lid = tid & 31;
    const int wm = wid & 3, wn = wid >> 2;

    const float* Ab  = V + (size_t)m0 * Ff;
    const float* Bh  = g_WTh + (size_t)nc * 64 * Ff;
    const float* Bl  = g_WTl + (size_t)nc * 64 * Ff;

    // ldmatrix quad addressing
    const int q = lid >> 3, rr = lid & 7;
    uint32_t aOff[2], bOff[2];
#pragma unroll
    for (int mt = 0; mt < 2; mt++)
        aOff[mt] = (uint32_t)((wm * 32 + mt * 16 + rr + (q & 1) * 8) * 128 + (q >> 1) * 16);
#pragma unroll
    for (int h = 0; h < 2; h++)
        bOff[h]  = (uint32_t)((wn * 32 + h * 16 + rr + (q >> 1) * 8) * 128 + (q & 1) * 16);

    float acc[2][4][4];
#pragma unroll
    for (int mt = 0; mt < 2; mt++)
#pragma unroll
        for (int nt = 0; nt < 4; nt++)
#pragma unroll
            for (int e = 0; e < 4; e++) acc[mt][nt][e] = 0.f;

    for (int kt = 0; kt < 2; kt++) {
        // stage A (hi/lo split)
#pragma unroll
        for (int it = 0; it < 4; it++) {
            const int idx = it * 256 + tid, row = idx >> 3, f4 = idx & 7;
            const float4 v = *(const float4*)(Ab + (size_t)row * Ff + kt * BK + f4 * 4);
            float4 h, l;
            h.x = to_tf32(v.x); l.x = to_tf32(v.x - h.x);
            h.y = to_tf32(v.y); l.y = to_tf32(v.y - h.y);
            h.z = to_tf32(v.z); l.z = to_tf32(v.z - h.z);
            h.w = to_tf32(v.w); l.w = to_tf32(v.w - h.w);
            const uint32_t off = sw128((uint32_t)(row * 128 + f4 * 16));
            *(float4*)((char*)sAhi + off) = h;
            *(float4*)((char*)sAlo + off) = l;
        }
        // stage B (already split in global)
#pragma unroll
        for (int it = 0; it < 2; it++) {
            const int idx = it * 256 + tid, row = idx >> 3, f4 = idx & 7;
            const uint32_t off = sw128((uint32_t)(row * 128 + f4 * 16));
            *(float4*)((char*)sBhi + off) = *(const float4*)(Bh + (size_t)row * Ff + kt * BK + f4 * 4);
            *(float4*)((char*)sBlo + off) = *(const float4*)(Bl + (size_t)row * Ff + kt * BK + f4 * 4);
        }
        __syncthreads();

#pragma unroll
        for (int ks = 0; ks < 4; ks++) {
            uint32_t afh[2][4], afl[2][4], bfh[2][4], bfl[2][4];
#pragma unroll
            for (int mt = 0; mt < 2; mt++) {
                uint32_t o = aOff[mt] + ks * 32, so = (o ^ ((o >> 3) & 0x70));
                LDSM_X4(afh[mt], aH + so);
                LDSM_X4(afl[mt], aL + so);
            }
#pragma unroll
            for (int h = 0; h < 2; h++) {
                uint32_t o = bOff[h] + ks * 32, so = (o ^ ((o >> 3) & 0x70));
                LDSM_X4(bfh[h], bH + so);
                LDSM_X4(bfl[h], bL + so);
            }
#pragma unroll
            for (int mt = 0; mt < 2; mt++)
#pragma unroll
                for (int nt = 0; nt < 4; nt++) {
                    const int hb = nt >> 1, eb = (nt & 1) * 2;
                    MMA_TF32(acc[mt][nt], afl[mt], bfh[hb][eb], bfh[hb][eb + 1]);
                    MMA_TF32(acc[mt][nt], afh[mt], bfl[hb][eb], bfl[hb][eb + 1]);
                    MMA_TF32(acc[mt][nt], afh[mt], bfh[hb][eb], bfh[hb][eb + 1]);
                }
        }
        __syncthreads();
    }

    // epilogue: route by N-chunk
    const int gid = lid >> 2, tig = lid & 3;
#pragma unroll
    for (int mt = 0; mt < 2; mt++)
#pragma unroll
        for (int nt = 0; nt < 4; nt++)
#pragma unroll
            for (int e = 0; e < 4; e++) {
                const int row = wm * 32 + mt * 16 + gid + (e >> 1) * 8;
                const int col = wn * 32 + nt * 8 + 2 * tig + (e & 1);
                const int m = m0 + row;
                const float v = acc[mt][nt][e];
                if (nc < 4) {
                    const int bb = m >> 11, j = m & 2047;
                    g_W3VT[((size_t)(bb * 64 + col)) * Kk + j * 4 + nc] = to_tf32(v);
                } else if (nc < 8) {
                    g_W2V[(size_t)m * 256 + (nc - 4) * 64 + col] = v;
                } else {
                    g_T1[(size_t)m * 64 + col] = v;
                }
            }
}

// ---------------- main GEMM: term3 + deg-from-fragments ----------------
// grid (16, Bdim, SPLITK), 256 threads (8 warps), warp tile 32x32.
__global__ __launch_bounds__(256, 3)
void gemm_kernel(const float* __restrict__ A) {
    __shared__ __align__(128) uint8_t smemRaw[49152];
    const uint32_t sm = smem_u32(smemRaw);
    const uint32_t sAu[2] = { sm, sm + 16384 };
    const uint32_t sBu[2] = { sm + 32768, sm + 40960 };
    float* degS = (float*)smemRaw;   // aliases sA0 after the main loop

    const int mtb = blockIdx.x, b = blockIdx.y, s = blockIdx.z;
    const int i0 = mtb * BM;
    const int t0 = (s * NTILES) / SPLITK, t1 = ((s + 1) * NTILES) / SPLITK;
    const int nkt = t1 - t0;
    const int tid = threadIdx.x, wid = tid >> 5, lid = tid & 31;
    const int wm = wid & 3, wn = wid >> 2;

    const float* Ab = A      + ((size_t)b * Nn + i0) * Kk;
    const float* Bb = g_W3VT + ((size_t)b * Cc) * Kk;

    auto issue = [&](int kt, int st) {
#pragma unroll
        for (int it = 0; it < 4; it++) {
            const int idx = it * 256 + tid, row = idx >> 3, f4 = idx & 7;
            CP16(sAu[st] + sw128((uint32_t)(row * 128 + f4 * 16)),
                 Ab + (size_t)row * Kk + kt * BK + f4 * 4);
        }
#pragma unroll
        for (int it = 0; it < 2; it++) {
            const int idx = it * 256 + tid, row = idx >> 3, f4 = idx & 7;
            CP16(sBu[st] + sw128((uint32_t)(row * 128 + f4 * 16)),
                 Bb + (size_t)row * Kk + kt * BK + f4 * 4);
        }
    };

    const int q = lid >> 3, rr = lid & 7;
    uint32_t aOff[2], bOff[2];
#pragma unroll
    for (int mt = 0; mt < 2; mt++)
        aOff[mt] = (uint32_t)((wm * 32 + mt * 16 + rr + (q & 1) * 8) * 128 + (q >> 1) * 16);
#pragma unroll
    for (int h = 0; h < 2; h++)
        bOff[h]  = (uint32_t)((wn * 32 + h * 16 + rr + (q >> 1) * 8) * 128 + (q & 1) * 16);

    float acc[2][4][4];
#pragma unroll
    for (int mt = 0; mt < 2; mt++)
#pragma unroll
        for (int nt = 0; nt < 4; nt++)
#pragma unroll
            for (int e = 0; e < 4; e++) acc[mt][nt][e] = 0.f;
    float dacc[4] = {0.f, 0.f, 0.f, 0.f};   // deg accum (wn==0 warps)

    issue(t0, 0); CPCOMMIT();
    if (nkt > 1) issue(t0 + 1, 1);
    CPCOMMIT();

    for (int qq = 0; qq < nkt; qq++) {
        const int st = qq & 1;
        CPWAIT(1);
        __syncthreads();
#pragma unroll
        for (int ks = 0; ks < 4; ks++) {
            uint32_t af[2][4], bf[2][4];
#pragma unroll
            for (int mt = 0; mt < 2; mt++) {
                uint32_t o = aOff[mt] + ks * 32;
                LDSM_X4(af[mt], sAu[st] + (o ^ ((o >> 3) & 0x70)));
            }
#pragma unroll
            for (int h = 0; h < 2; h++) {
                uint32_t o = bOff[h] + ks * 32;
                LDSM_X4(bf[h], sBu[st] + (o ^ ((o >> 3) & 0x70)));
            }
            if (wn == 0) {   // deg from A fragments: l = lane&3 exactly
#pragma unroll
                for (int mt = 0; mt < 2; mt++) {
                    dacc[mt * 2]     += __uint_as_float(af[mt][0]) + __uint_as_float(af[mt][2]);
                    dacc[mt * 2 + 1] += __uint_as_float(af[mt][1]) + __uint_as_float(af[mt][3]);
                }
            }
#pragma unroll
            for (int mt = 0; mt < 2; mt++)
#pragma unroll
                for (int nt = 0; nt < 4; nt++)
                    MMA_TF32(acc[mt][nt], af[mt], bf[nt >> 1][(nt & 1) * 2], bf[nt >> 1][(nt & 1) * 2 + 1]);
        }
        __syncthreads();
        if (qq + 2 < nkt) issue(t0 + qq + 2, st);
        CPCOMMIT();
    }

    // deg: unique (row, l) per thread among wn==0 warps -> plain stores
    const int gid = lid >> 2, tig = lid & 3;
    __syncthreads();
    if (wn == 0) {
#pragma unroll
        for (int i = 0; i < 4; i++) {
            const int row = wm * 32 + (i >> 1) * 16 + (i & 1) * 8 + gid;
            degS[row * 4 + tig] = dacc[i];
        }
    }
    __syncthreads();

    // write partials
    float* outp = g_part + (((size_t)s * Bdim + b) * Nn + i0) * PARTW;
#pragma unroll
    for (int mt = 0; mt < 2; mt++)
#pragma unroll
        for (int nt = 0; nt < 4; nt++) {
            const int r0 = wm * 32 + mt * 16 + gid;
            const int cc = wn * 32 + nt * 8 + 2 * tig;
            float2 v0; v0.x = acc[mt][nt][0]; v0.y = acc[mt][nt][1];
            float2 v1; v1.x = acc[mt][nt][2]; v1.y = acc[mt][nt][3];
            *(float2*)(outp + (size_t)r0 * PARTW + cc)       = v0;
            *(float2*)(outp + (size_t)(r0 + 8) * PARTW + cc) = v1;
        }
#pragma unroll
    for (int it = 0; it < 2; it++) {
        const int idx = it * 256 + tid;    // row*4 + l
        outp[(size_t)(idx >> 2) * PARTW + 64 + (idx & 3)] = degS[idx];
    }
}

// ---------------- epilogue: combine terms + sigmoid ----------------
// grid (Nn/4, Bdim), 256 threads: 4 rows per block, 64 channels per row.
// deg partials read as one aligned float4 per split (row base ≡ 0 mod 16B).
__global__ __launch_bounds__(256)
void epilogue_kernel(float* __restrict__ out) {
    const int tid = threadIdx.x;
    const int c = tid & 63, r = tid >> 6;
    const int i = blockIdx.x * 4 + r, b = blockIdx.y;
    const size_t row = (size_t)b * Nn + i;

    float t3 = 0.f, d0 = 0.f, d1 = 0.f, d2 = 0.f, d3 = 0.f;
#pragma unroll
    for (int s = 0; s < SPLITK; s++) {
        const float* p = g_part + (((size_t)s * Bdim + b) * Nn + i) * PARTW;
        t3 += p[c];
        const float4 dv = *(const float4*)(p + 64);
        d0 += dv.x; d1 += dv.y; d2 += dv.z; d3 += dv.w;
    }
    const float* w2v = g_W2V + row * (Ll * Cc);
    const float x = g_T1[row * Cc + c]
                  + d0 * w2v[0 * Cc + c] + d1 * w2v[1 * Cc + c]
                  + d2 * w2v[2 * Cc + c] + d3 * w2v[3 * Cc + c]
                  - t3;
    out[row * Cc + c] = 1.f / (1.f + expf(-x));
}

// ---------------- launch ----------------
extern "C" void kernel_launch(void* const* d_in, const int* in_sizes, int n_in,
                              void* d_out, int out_size) {
    const float* V  = (const float*)d_in[0];
    const float* A  = (const float*)d_in[1];
    const float* w1 = (const float*)d_in[2];
    const float* w2 = (const float*)d_in[3];
    const float* w3 = (const float*)d_in[4];
    float* out = (float*)d_out;

    wtrans_kernel<<<576, 64>>>(w1, w2, w3);
    pregemm_kernel<<<dim3(32, 9), 256>>>(V);
    gemm_kernel<<<dim3(Nn / BM, Bdim, SPLITK), 256>>>(A);
    epilogue_kernel<<<dim3(Nn / 4, Bdim), 256>>>(out);
}